// round 11
// baseline (speedup 1.0000x reference)
#include <cuda_runtime.h>

// ---------------- constants ----------------
#define G       100
#define G3      (G * G * G)
#define NPART   13500
#define NSUB    600
#define SPF     30
#define BOUNDC  3
#define NTHR    128

#define DT_     5e-4f
#define INVDX_  100.0f
#define DX_     0.01f
#define MU_     (1.0e5f / 2.6f)
#define LAM_    (0.3e5f / 0.52f)
#define PVOL_   (0.005f * 0.005f * 0.005f)
#define PMASS_  (PVOL_ * 3000.0f)
#define SPRE_   (-DT_ * PVOL_ * 4.0f * INVDX_ * INVDX_)
#define DINV_   (4.0f * INVDX_ * INVDX_)
#define GRAVY_  (-9.8f)

// ---------------- persistent device state ----------------
__device__ float4 g_grid[3][G3];          // (vx,vy,vz,m) x 3 rotating buffers
__device__ unsigned g_bar_count;
__device__ volatile unsigned g_bar_gen;

// ---------------- helpers ----------------
__device__ __forceinline__ float wsel(int o, float a, float b, float c) {
    return (o == 0) ? a : ((o == 1) ? b : c);
}

// reduce across 4-lane subgroup (warp-uniform: every lane participates)
#define GRED4(v)                                              \
    do {                                                      \
        v += __shfl_xor_sync(0xffffffffu, v, 2);              \
        v += __shfl_xor_sync(0xffffffffu, v, 1);              \
    } while (0)

// release/acquire grid-wide barrier; all gridDim.x blocks are co-resident
// (grid sized to 3 blocks/SM at launch, enforced by __launch_bounds__)
__device__ __forceinline__ void grid_barrier() {
    __syncthreads();
    if (threadIdx.x == 0) {
        __threadfence();
        unsigned gen = g_bar_gen;
        if (atomicAdd(&g_bar_count, 1u) == gridDim.x - 1) {
            g_bar_count = 0;
            __threadfence();
            g_bar_gen = gen + 1;
        } else {
            while (g_bar_gen == gen) __nanosleep(32);
        }
        __threadfence();
    }
    __syncthreads();
}

// ---------------- the megakernel: 4 lanes per particle, 8 particles/warp ----
__global__ void __launch_bounds__(NTHR, 3) k_mpm_mega(
    const float* __restrict__ vptr, const float* __restrict__ q,
    const float* __restrict__ qd, float* __restrict__ out)
{
    const int tid = blockIdx.x * NTHR + threadIdx.x;
    const int nthreads = gridDim.x * NTHR;
    const int lane = threadIdx.x & 31;
    const int sl = lane & 3;                       // lane within particle subgroup
    const int praw = (tid >> 5) * 8 + (lane >> 2);
    const bool real = (praw < NPART);              // only reals produce side effects
    const int p = real ? praw : (NPART - 1);       // clamped: uniform warp execution
    const float vscalar = __ldg(vptr);
    const float4 zero4 = make_float4(0.f, 0.f, 0.f, 0.f);

    // stencil decode for this lane's up-to-7 cells, constant for the whole run
    int OI[7], OJ[7], OK[7];
    bool CA[7];
#pragma unroll
    for (int k = 0; k < 7; k++) {
        int c = sl + 4 * k;
        CA[k] = (c < 27);
        int ci = c < 27 ? c : 0;
        OI[k] = ci / 9;
        OJ[k] = (ci / 3) % 3;
        OK[k] = ci % 3;
    }

    // ---- init: zero all 3 grid buffers ----
    for (int i = tid; i < 3 * G3; i += nthreads)
        __stcg(&reinterpret_cast<float4*>(g_grid)[i], zero4);

    // ---- particle state in registers for the whole run ----
    float px = __ldg(&q[p * 3 + 0]);
    float py = __ldg(&q[p * 3 + 1]);
    float pz = __ldg(&q[p * 3 + 2]);
    float v0x = __ldg(&qd[p * 3 + 0]);
    float v0y = __ldg(&qd[p * 3 + 1]);
    float v0z = __ldg(&qd[p * 3 + 2]);
    float F00 = 1.f, F01 = 0.f, F02 = 0.f;
    float F10 = 0.f, F11 = 1.f, F12 = 0.f;
    float F20 = 0.f, F21 = 0.f, F22 = 1.f;
    int bh_old = 0, bh_new = 0;   // packed base-cell history (7 bits/axis, +1 biased)

    grid_barrier();

#pragma unroll 1
    for (int t = 1; t <= NSUB; t++) {
        const int bufG = (t + 2) % 3;
        const int bufS = t % 3;
        const int bufZ = (t + 1) % 3;

        // --- zero touched cells of the t-2 buffer (side effect: reals only) ---
        if (t >= 3 && real) {
            int obz = (bh_old & 127) - 1, oby = ((bh_old >> 7) & 127) - 1,
                obx = ((bh_old >> 14) & 127) - 1;
#pragma unroll
            for (int k = 0; k < 7; k++) if (CA[k]) {
                int nx = min(max(obx + OI[k], 0), G - 1);
                int ny = min(max(oby + OJ[k], 0), G - 1);
                int nz = min(max(obz + OK[k], 0), G - 1);
                __stcg(&g_grid[bufZ][(nx * G + ny) * G + nz], zero4);
            }
        }

        float vx, vy, vz;
        float c00, c01, c02, c10, c11, c12, c20, c21, c22;

        if (t >= 2) {
            // --- G2P for substep t-1 (uniform across warp; clamped p is safe) ---
            float gx = px * INVDX_, gy = py * INVDX_, gz = pz * INVDX_;
            float bxf = floorf(gx - 0.5f), byf = floorf(gy - 0.5f), bzf = floorf(gz - 0.5f);
            int bx = (int)bxf, by = (int)byf, bz = (int)bzf;
            float fx = gx - bxf, fy = gy - byf, fz = gz - bzf;

            float wx0 = 0.5f * (1.5f - fx) * (1.5f - fx);
            float wx1 = 0.75f - (fx - 1.0f) * (fx - 1.0f);
            float wx2 = 0.5f * (fx - 0.5f) * (fx - 0.5f);
            float wy0 = 0.5f * (1.5f - fy) * (1.5f - fy);
            float wy1 = 0.75f - (fy - 1.0f) * (fy - 1.0f);
            float wy2 = 0.5f * (fy - 0.5f) * (fy - 0.5f);
            float wz0 = 0.5f * (1.5f - fz) * (1.5f - fz);
            float wz1 = 0.75f - (fz - 1.0f) * (fz - 1.0f);
            float wz2 = 0.5f * (fz - 0.5f) * (fz - 0.5f);

            vx = vy = vz = 0.f;
            c00 = c01 = c02 = c10 = c11 = c12 = c20 = c21 = c22 = 0.f;

#pragma unroll
            for (int k = 0; k < 7; k++) if (CA[k]) {
                int oi = OI[k], oj = OJ[k], ok = OK[k];
                float w = wsel(oi, wx0, wx1, wx2) * wsel(oj, wy0, wy1, wy2) * wsel(ok, wz0, wz1, wz2);
                int nx = min(max(bx + oi, 0), G - 1);
                int ny = min(max(by + oj, 0), G - 1);
                int nz = min(max(bz + ok, 0), G - 1);
                float4 cell = __ldcg(&g_grid[bufG][(nx * G + ny) * G + nz]);

                float inv = __fdividef(1.0f, cell.w + vscalar);
                float gvx = cell.x * inv, gvy = cell.y * inv, gvz = cell.z * inv;
                if ((nx < BOUNDC && gvx < 0.f) || (nx >= G - BOUNDC && gvx > 0.f)) gvx = 0.f;
                if ((ny < BOUNDC && gvy < 0.f) || (ny >= G - BOUNDC && gvy > 0.f)) gvy = 0.f;
                if ((nz < BOUNDC && gvz < 0.f) || (nz >= G - BOUNDC && gvz > 0.f)) gvz = 0.f;

                float dpx = ((float)oi - fx) * DX_;
                float dpy = ((float)oj - fy) * DX_;
                float dpz = ((float)ok - fz) * DX_;

                float wgx = w * gvx, wgy = w * gvy, wgz = w * gvz;
                vx += wgx; vy += wgy; vz += wgz;
                c00 += wgx * dpx; c01 += wgx * dpy; c02 += wgx * dpz;
                c10 += wgy * dpx; c11 += wgy * dpy; c12 += wgy * dpz;
                c20 += wgz * dpx; c21 += wgz * dpy; c22 += wgz * dpz;
            }

            GRED4(vx);  GRED4(vy);  GRED4(vz);
            GRED4(c00); GRED4(c01); GRED4(c02);
            GRED4(c10); GRED4(c11); GRED4(c12);
            GRED4(c20); GRED4(c21); GRED4(c22);

            c00 *= DINV_; c01 *= DINV_; c02 *= DINV_;
            c10 *= DINV_; c11 *= DINV_; c12 *= DINV_;
            c20 *= DINV_; c21 *= DINV_; c22 *= DINV_;

            px += DT_ * vx; py += DT_ * vy; pz += DT_ * vz;
        } else {
            vx = v0x; vy = v0y; vz = v0z;
            c00 = c01 = c02 = c10 = c11 = c12 = c20 = c21 = c22 = 0.f;
        }

        // --- F = (I + DT*C) * F ---
        float a00 = 1.0f + DT_ * c00, a01 = DT_ * c01, a02 = DT_ * c02;
        float a10 = DT_ * c10, a11 = 1.0f + DT_ * c11, a12 = DT_ * c12;
        float a20 = DT_ * c20, a21 = DT_ * c21, a22 = 1.0f + DT_ * c22;

        float N00 = a00 * F00 + a01 * F10 + a02 * F20;
        float N01 = a00 * F01 + a01 * F11 + a02 * F21;
        float N02 = a00 * F02 + a01 * F12 + a02 * F22;
        float N10 = a10 * F00 + a11 * F10 + a12 * F20;
        float N11 = a10 * F01 + a11 * F11 + a12 * F21;
        float N12 = a10 * F02 + a11 * F12 + a12 * F22;
        float N20 = a20 * F00 + a21 * F10 + a22 * F20;
        float N21 = a20 * F01 + a21 * F11 + a22 * F21;
        float N22 = a20 * F02 + a21 * F12 + a22 * F22;
        F00 = N00; F01 = N01; F02 = N02;
        F10 = N10; F11 = N11; F12 = N12;
        F20 = N20; F21 = N21; F22 = N22;

        // --- neo-Hookean PK1 via cofactors ---
        float co00 = F11 * F22 - F12 * F21;
        float co01 = F12 * F20 - F10 * F22;
        float co02 = F10 * F21 - F11 * F20;
        float co10 = F02 * F21 - F01 * F22;
        float co11 = F00 * F22 - F02 * F20;
        float co12 = F01 * F20 - F00 * F21;
        float co20 = F01 * F12 - F02 * F11;
        float co21 = F02 * F10 - F00 * F12;
        float co22 = F00 * F11 - F01 * F10;
        float J = F00 * co00 + F01 * co01 + F02 * co02;

        float logJ = __logf(fmaxf(J, 1e-6f));
        float coef = __fdividef(LAM_ * logJ - MU_, J);

        float P00 = MU_ * F00 + coef * co00;
        float P01 = MU_ * F01 + coef * co01;
        float P02 = MU_ * F02 + coef * co02;
        float P10 = MU_ * F10 + coef * co10;
        float P11 = MU_ * F11 + coef * co11;
        float P12 = MU_ * F12 + coef * co12;
        float P20 = MU_ * F20 + coef * co20;
        float P21 = MU_ * F21 + coef * co21;
        float P22 = MU_ * F22 + coef * co22;

        float A00 = SPRE_ * (P00 * F00 + P01 * F01 + P02 * F02) + PMASS_ * c00;
        float A01 = SPRE_ * (P00 * F10 + P01 * F11 + P02 * F12) + PMASS_ * c01;
        float A02 = SPRE_ * (P00 * F20 + P01 * F21 + P02 * F22) + PMASS_ * c02;
        float A10 = SPRE_ * (P10 * F00 + P11 * F01 + P12 * F02) + PMASS_ * c10;
        float A11 = SPRE_ * (P10 * F10 + P11 * F11 + P12 * F12) + PMASS_ * c11;
        float A12 = SPRE_ * (P10 * F20 + P11 * F21 + P12 * F22) + PMASS_ * c12;
        float A20 = SPRE_ * (P20 * F00 + P21 * F01 + P22 * F02) + PMASS_ * c20;
        float A21 = SPRE_ * (P20 * F10 + P21 * F11 + P22 * F12) + PMASS_ * c21;
        float A22 = SPRE_ * (P20 * F20 + P21 * F21 + P22 * F22) + PMASS_ * c22;

        // --- P2G for substep t ---
        float gx2 = px * INVDX_, gy2 = py * INVDX_, gz2 = pz * INVDX_;
        float bxf2 = floorf(gx2 - 0.5f), byf2 = floorf(gy2 - 0.5f), bzf2 = floorf(gz2 - 0.5f);
        int bx2 = (int)bxf2, by2 = (int)byf2, bz2 = (int)bzf2;
        float fx2 = gx2 - bxf2, fy2 = gy2 - byf2, fz2 = gz2 - bzf2;

        float sx0 = 0.5f * (1.5f - fx2) * (1.5f - fx2);
        float sx1 = 0.75f - (fx2 - 1.0f) * (fx2 - 1.0f);
        float sx2 = 0.5f * (fx2 - 0.5f) * (fx2 - 0.5f);
        float sy0 = 0.5f * (1.5f - fy2) * (1.5f - fy2);
        float sy1 = 0.75f - (fy2 - 1.0f) * (fy2 - 1.0f);
        float sy2 = 0.5f * (fy2 - 0.5f) * (fy2 - 0.5f);
        float sz0 = 0.5f * (1.5f - fz2) * (1.5f - fz2);
        float sz1 = 0.75f - (fz2 - 1.0f) * (fz2 - 1.0f);
        float sz2 = 0.5f * (fz2 - 0.5f) * (fz2 - 0.5f);

        float mvx = PMASS_ * vx;
        float mvy = PMASS_ * (vy + DT_ * GRAVY_);
        float mvz = PMASS_ * vz;

        bh_old = bh_new;
        bh_new = ((bx2 + 1) << 14) | ((by2 + 1) << 7) | (bz2 + 1);

        if (real) {
#pragma unroll
            for (int k = 0; k < 7; k++) if (CA[k]) {
                int oi = OI[k], oj = OJ[k], ok = OK[k];
                float w2 = wsel(oi, sx0, sx1, sx2) * wsel(oj, sy0, sy1, sy2) * wsel(ok, sz0, sz1, sz2);
                float dpx = ((float)oi - fx2) * DX_;
                float dpy = ((float)oj - fy2) * DX_;
                float dpz = ((float)ok - fz2) * DX_;

                float mx = w2 * (mvx + A00 * dpx + A01 * dpy + A02 * dpz);
                float my = w2 * (mvy + A10 * dpx + A11 * dpy + A12 * dpz);
                float mz = w2 * (mvz + A20 * dpx + A21 * dpy + A22 * dpz);
                float mw = w2 * PMASS_;

                int nx = min(max(bx2 + oi, 0), G - 1);
                int ny = min(max(by2 + oj, 0), G - 1);
                int nz = min(max(bz2 + ok, 0), G - 1);
                float4* cell = &g_grid[bufS][(nx * G + ny) * G + nz];
                asm volatile("red.global.add.v4.f32 [%0], {%1, %2, %3, %4};"
                             :: "l"(cell), "f"(mx), "f"(my), "f"(mz), "f"(mw)
                             : "memory");
            }
        }

        grid_barrier();

        // --- frame output ---
        if (t % SPF == 0) {
            const int f = t / SPF - 1;
            float* dst = out + (size_t)f * G3;
            const float4* src = g_grid[bufS];
            for (int i = tid; i < G3; i += nthreads)
                dst[i] = __ldcg(&src[i].w) + vscalar;
        }
    }
}

// ---------------- launcher ----------------
extern "C" void kernel_launch(void* const* d_in, const int* in_sizes, int n_in,
                              void* d_out, int out_size) {
    const float* v  = (const float*)d_in[0];
    const float* q  = (const float*)d_in[1];
    const float* qd = (const float*)d_in[2];
    float* out = (float*)d_out;
    (void)in_sizes; (void)n_in; (void)out_size;

    // Grid must be fully co-resident for the spin barrier: 3 blocks/SM
    // (guaranteed by __launch_bounds__(128, 3)), sized from the real SM count.
    int nsm = 0;
    cudaDeviceGetAttribute(&nsm, cudaDevAttrMultiProcessorCount, 0);
    if (nsm <= 0) nsm = 148;
    int nblk = 3 * nsm;   // 444 (148 SMs) / 456 (152 SMs); need >= 422 for warps

    k_mpm_mega<<<nblk, NTHR>>>(v, q, qd, out);
}